// round 13
// baseline (speedup 1.0000x reference)
#include <cuda_runtime.h>
#include <cstdint>

#define L_LEVELS 12
#define T_SIZE   (1u << 19)
#define T_MASK   (T_SIZE - 1u)
#define N_POINTS 524288
#define D_OUT    257
#define FEAT     24          // L * F
#define BLOCK    64          // threads per block = points per block (2 warps)
#define EMB_PAD  28          // padded row stride in floats

#define SORT_RES 32
#define NBINS    (SORT_RES * SORT_RES * SORT_RES)   // 32768

// ---------------- scratch (device globals: alloc-rule-safe) ----------------
__device__ int    g_hist[NBINS];
__device__ float4 g_xyzp[N_POINTS];   // sorted {x,y,z, bitcast(orig index)}

// ---------- packed f32x2 helpers (Blackwell FFMA2 path) ----------
__device__ __forceinline__ unsigned long long pack2(float lo, float hi) {
    unsigned long long r;
    asm("mov.b64 %0, {%1, %2};" : "=l"(r) : "f"(lo), "f"(hi));
    return r;
}
__device__ __forceinline__ void unpack2(unsigned long long v, float& lo, float& hi) {
    asm("mov.b64 {%0, %1}, %2;" : "=f"(lo), "=f"(hi) : "l"(v));
}
__device__ __forceinline__ unsigned long long fma2(unsigned long long a,
                                                   unsigned long long b,
                                                   unsigned long long c) {
    unsigned long long d;
    asm("fma.rn.f32x2 %0, %1, %2, %3;" : "=l"(d) : "l"(a), "l"(b), "l"(c));
    return d;
}

__device__ __constant__ float RESF[L_LEVELS] = {
    16.f, 24.f, 38.f, 60.f, 93.f, 145.f, 225.f, 350.f, 545.f, 847.f, 1317.f, 2048.f
};

__device__ __forceinline__ int cell_key(float x, float y, float z) {
    int cx = (int)(x * SORT_RES); cx = cx > SORT_RES - 1 ? SORT_RES - 1 : cx;
    int cy = (int)(y * SORT_RES); cy = cy > SORT_RES - 1 ? SORT_RES - 1 : cy;
    int cz = (int)(z * SORT_RES); cz = cz > SORT_RES - 1 ? SORT_RES - 1 : cz;
    return (cz * SORT_RES + cy) * SORT_RES + cx;
}

// -------- K1: histogram --------
__global__ void hist_kernel(const float* __restrict__ xin) {
    int p = blockIdx.x * blockDim.x + threadIdx.x;
    float x = xin[3 * p], y = xin[3 * p + 1], z = xin[3 * p + 2];
    atomicAdd(&g_hist[cell_key(x, y, z)], 1);
}

// -------- K2: exclusive prefix sum over NBINS (single block, 1024 threads) ----
__global__ void scan_kernel() {
    __shared__ int ssum[1024];
    const int tid = threadIdx.x;
    const int CH = NBINS / 1024;   // 32
    int local[CH];
    int tot = 0;
#pragma unroll
    for (int i = 0; i < CH; i++) { local[i] = g_hist[tid * CH + i]; tot += local[i]; }
    ssum[tid] = tot;
    __syncthreads();
    // Hillis-Steele inclusive scan over 1024
    for (int off = 1; off < 1024; off <<= 1) {
        int v = (tid >= off) ? ssum[tid - off] : 0;
        __syncthreads();
        ssum[tid] += v;
        __syncthreads();
    }
    int run = ssum[tid] - tot;   // exclusive base for this chunk
#pragma unroll
    for (int i = 0; i < CH; i++) { g_hist[tid * CH + i] = run; run += local[i]; }
}

// -------- K3: scatter into sorted order --------
__global__ void scatter_kernel(const float* __restrict__ xin) {
    int p = blockIdx.x * blockDim.x + threadIdx.x;
    float x = xin[3 * p], y = xin[3 * p + 1], z = xin[3 * p + 2];
    int pos = atomicAdd(&g_hist[cell_key(x, y, z)], 1);
    g_xyzp[pos] = make_float4(x, y, z, __int_as_float(p));
}

// -------- K4: main fused kernel (R2 structure, sorted inputs) --------
__global__ __launch_bounds__(BLOCK, 8)
void hashgrid_fused_kernel(const float2* __restrict__ tab,    // [12, T] of float2
                           const float*  __restrict__ W,      // [24, 257]
                           const float*  __restrict__ bias,   // [257]
                           float*        __restrict__ out)    // [N, 257]
{
    __shared__ float semb[BLOCK][EMB_PAD];
    __shared__ int   sp[BLOCK];            // original point index per row
    __shared__ float wc256[FEAT];
    __shared__ float b256s;

    const int tid = threadIdx.x;

    if (tid < FEAT) wc256[tid] = W[tid * D_OUT + 256];
    if (tid == FEAT) b256s = bias[256];
    __syncthreads();

    // ---------------- Phase 1: hash encode (thread = sorted point) -------------
    const float4 xp = g_xyzp[blockIdx.x * BLOCK + tid];   // coalesced
    const float x = xp.x, y = xp.y, z = xp.z;
    const int p = __float_as_int(xp.w);
    sp[tid] = p;

    const unsigned P1 = 2654435761u;
    const unsigned P2 = 805459861u;

    float acc256 = b256s;

#pragma unroll
    for (int l = 0; l < L_LEVELS; l++) {
        const float resf = RESF[l];
        const float2* tl = tab + (size_t)l * T_SIZE;

        float px = x * resf, py = y * resf, pz = z * resf;
        float fx = floorf(px), fy = floorf(py), fz = floorf(pz);
        float tx = px - fx,   ty = py - fy,   tz = pz - fz;

        unsigned cx = (unsigned)fx, cy = (unsigned)fy, cz = (unsigned)fz;
        unsigned hx0 = cx,        hx1 = cx + 1u;
        unsigned hy0 = cy * P1,   hy1 = hy0 + P1;
        unsigned hz0 = cz * P2,   hz1 = hz0 + P2;

        float2 f[8];
        f[0] = __ldg(tl + ((hx0 ^ hy0 ^ hz0) & T_MASK));
        f[1] = __ldg(tl + ((hx0 ^ hy0 ^ hz1) & T_MASK));
        f[2] = __ldg(tl + ((hx0 ^ hy1 ^ hz0) & T_MASK));
        f[3] = __ldg(tl + ((hx0 ^ hy1 ^ hz1) & T_MASK));
        f[4] = __ldg(tl + ((hx1 ^ hy0 ^ hz0) & T_MASK));
        f[5] = __ldg(tl + ((hx1 ^ hy0 ^ hz1) & T_MASK));
        f[6] = __ldg(tl + ((hx1 ^ hy1 ^ hz0) & T_MASK));
        f[7] = __ldg(tl + ((hx1 ^ hy1 ^ hz1) & T_MASK));

        const float ux = 1.0f - tx, uy = 1.0f - ty, uz = 1.0f - tz;
        float wxy[4];
        wxy[0] = ux * uy;
        wxy[1] = ux * ty;
        wxy[2] = tx * uy;
        wxy[3] = tx * ty;

        float e0 = 0.0f, e1 = 0.0f;
#pragma unroll
        for (int i = 0; i < 8; i++) {
            float w = wxy[i >> 1] * ((i & 1) ? tz : uz);
            e0 = fmaf(w, f[i].x, e0);
            e1 = fmaf(w, f[i].y, e1);
        }

        *reinterpret_cast<float2*>(&semb[tid][2 * l]) = make_float2(e0, e1);
        acc256 = fmaf(e0, wc256[2 * l + 0], acc256);
        acc256 = fmaf(e1, wc256[2 * l + 1], acc256);
    }

    // odd 257th column
    __stcs(out + (size_t)p * D_OUT + 256, acc256);

    __syncthreads();

    // ------- Phase 2: GEMM head. Thread owns 4 strided columns. -------
    unsigned long long wreg[L_LEVELS][4];
#pragma unroll
    for (int kk = 0; kk < L_LEVELS; kk++) {
#pragma unroll
        for (int c = 0; c < 4; c++) {
            int col = tid + 64 * c;
            wreg[kk][c] = pack2(W[(2 * kk) * D_OUT + col], W[(2 * kk + 1) * D_OUT + col]);
        }
    }
    float breg[4];
#pragma unroll
    for (int c = 0; c < 4; c++) breg[c] = bias[tid + 64 * c];

#pragma unroll 2
    for (int r = 0; r < BLOCK; r++) {
        const float4* erow = reinterpret_cast<const float4*>(&semb[r][0]);
        unsigned long long a0 = 0, a1 = 0, a2 = 0, a3 = 0;
#pragma unroll
        for (int q = 0; q < 6; q++) {
            float4 e4 = erow[q];                 // broadcast LDS.128
            unsigned long long p0 = pack2(e4.x, e4.y);
            unsigned long long p1 = pack2(e4.z, e4.w);
            a0 = fma2(p0, wreg[2 * q][0], a0);  a0 = fma2(p1, wreg[2 * q + 1][0], a0);
            a1 = fma2(p0, wreg[2 * q][1], a1);  a1 = fma2(p1, wreg[2 * q + 1][1], a1);
            a2 = fma2(p0, wreg[2 * q][2], a2);  a2 = fma2(p1, wreg[2 * q + 1][2], a2);
            a3 = fma2(p0, wreg[2 * q][3], a3);  a3 = fma2(p1, wreg[2 * q + 1][3], a3);
        }
        float lo, hi;
        float* orow = out + (size_t)sp[r] * D_OUT;   // original row (stores stay 128B-coalesced)
        unpack2(a0, lo, hi); __stcs(orow + tid,       lo + hi + breg[0]);
        unpack2(a1, lo, hi); __stcs(orow + tid +  64, lo + hi + breg[1]);
        unpack2(a2, lo, hi); __stcs(orow + tid + 128, lo + hi + breg[2]);
        unpack2(a3, lo, hi); __stcs(orow + tid + 192, lo + hi + breg[3]);
    }
}

extern "C" void kernel_launch(void* const* d_in, const int* in_sizes, int n_in,
                              void* d_out, int out_size) {
    const float*  xin  = (const float*) d_in[0];   // [N,3]
    const float2* tab  = (const float2*)d_in[1];   // [12,T,2] -> float2
    const float*  W    = (const float*) d_in[2];   // [24,257]
    const float*  bias = (const float*) d_in[3];   // [257]
    float* out = (float*)d_out;

    static void* hist_ptr = nullptr;
    if (!hist_ptr) cudaGetSymbolAddress(&hist_ptr, g_hist);

    cudaMemsetAsync(hist_ptr, 0, NBINS * sizeof(int));
    hist_kernel<<<N_POINTS / 256, 256>>>(xin);
    scan_kernel<<<1, 1024>>>();
    scatter_kernel<<<N_POINTS / 256, 256>>>(xin);
    hashgrid_fused_kernel<<<N_POINTS / BLOCK, BLOCK>>>(tab, W, bias, out);
}

// round 15
// speedup vs baseline: 1.0496x; 1.0496x over previous
#include <cuda_runtime.h>
#include <cstdint>

#define L_LEVELS 12
#define T_SIZE   (1u << 19)
#define T_MASK   (T_SIZE - 1u)
#define N_POINTS 524288
#define D_OUT    257
#define FEAT     24          // L * F
#define BLOCK    64          // threads per block = points per block (2 warps)
#define EMB_PAD  28          // padded row stride in floats

#define SORT_RES 32
#define NBINS    (SORT_RES * SORT_RES * SORT_RES)   // 32768

// ---------------- scratch (device globals: alloc-rule-safe) ----------------
__device__ int    g_hist[NBINS];
__device__ float4 g_xyzp[N_POINTS];   // sorted {x,y,z, bitcast(orig index)}

// ---------- packed f32x2 helpers (Blackwell FFMA2 path) ----------
__device__ __forceinline__ unsigned long long pack2(float lo, float hi) {
    unsigned long long r;
    asm("mov.b64 %0, {%1, %2};" : "=l"(r) : "f"(lo), "f"(hi));
    return r;
}
__device__ __forceinline__ void unpack2(unsigned long long v, float& lo, float& hi) {
    asm("mov.b64 {%0, %1}, %2;" : "=f"(lo), "=f"(hi) : "l"(v));
}
__device__ __forceinline__ unsigned long long fma2(unsigned long long a,
                                                   unsigned long long b,
                                                   unsigned long long c) {
    unsigned long long d;
    asm("fma.rn.f32x2 %0, %1, %2, %3;" : "=l"(d) : "l"(a), "l"(b), "l"(c));
    return d;
}

__device__ __constant__ float RESF[L_LEVELS] = {
    16.f, 24.f, 38.f, 60.f, 93.f, 145.f, 225.f, 350.f, 545.f, 847.f, 1317.f, 2048.f
};

__device__ __forceinline__ int cell_key(float x, float y, float z) {
    int cx = (int)(x * SORT_RES); cx = cx > SORT_RES - 1 ? SORT_RES - 1 : cx;
    int cy = (int)(y * SORT_RES); cy = cy > SORT_RES - 1 ? SORT_RES - 1 : cy;
    int cz = (int)(z * SORT_RES); cz = cz > SORT_RES - 1 ? SORT_RES - 1 : cz;
    return (cz * SORT_RES + cy) * SORT_RES + cx;
}

// -------- K1: histogram --------
__global__ void hist_kernel(const float* __restrict__ xin) {
    int p = blockIdx.x * blockDim.x + threadIdx.x;
    float x = xin[3 * p], y = xin[3 * p + 1], z = xin[3 * p + 2];
    atomicAdd(&g_hist[cell_key(x, y, z)], 1);
}

// -------- K2: exclusive prefix sum over NBINS, COALESCED (single block) ----
__global__ void scan_kernel() {
    __shared__ int warp_sums[32];
    const int tid = threadIdx.x;
    const int lane = tid & 31;
    const int wid = tid >> 5;

    int carry = 0;   // running total, replicated across all threads

    for (int c = 0; c < NBINS; c += 1024) {
        int v = g_hist[c + tid];          // coalesced: 1024 consecutive ints

        // warp-level inclusive scan via shfl
        int s = v;
#pragma unroll
        for (int o = 1; o < 32; o <<= 1) {
            int n = __shfl_up_sync(0xffffffffu, s, o);
            if (lane >= o) s += n;
        }
        if (lane == 31) warp_sums[wid] = s;
        __syncthreads();

        // warp 0 scans the 32 warp sums (inclusive)
        if (wid == 0) {
            int ws = warp_sums[lane];
#pragma unroll
            for (int o = 1; o < 32; o <<= 1) {
                int n = __shfl_up_sync(0xffffffffu, ws, o);
                if (lane >= o) ws += n;
            }
            warp_sums[lane] = ws;
        }
        __syncthreads();

        int wbase = (wid > 0) ? warp_sums[wid - 1] : 0;
        int total = warp_sums[31];
        g_hist[c + tid] = carry + wbase + s - v;   // exclusive, coalesced
        carry += total;
        __syncthreads();   // protect warp_sums before next iteration
    }
}

// -------- K3: scatter into sorted order --------
__global__ void scatter_kernel(const float* __restrict__ xin) {
    int p = blockIdx.x * blockDim.x + threadIdx.x;
    float x = xin[3 * p], y = xin[3 * p + 1], z = xin[3 * p + 2];
    int pos = atomicAdd(&g_hist[cell_key(x, y, z)], 1);
    g_xyzp[pos] = make_float4(x, y, z, __int_as_float(p));
}

// -------- K4: main fused kernel (identical to R13) --------
__global__ __launch_bounds__(BLOCK, 8)
void hashgrid_fused_kernel(const float2* __restrict__ tab,    // [12, T] of float2
                           const float*  __restrict__ W,      // [24, 257]
                           const float*  __restrict__ bias,   // [257]
                           float*        __restrict__ out)    // [N, 257]
{
    __shared__ float semb[BLOCK][EMB_PAD];
    __shared__ int   sp[BLOCK];            // original point index per row
    __shared__ float wc256[FEAT];
    __shared__ float b256s;

    const int tid = threadIdx.x;

    if (tid < FEAT) wc256[tid] = W[tid * D_OUT + 256];
    if (tid == FEAT) b256s = bias[256];
    __syncthreads();

    // ---------------- Phase 1: hash encode (thread = sorted point) -------------
    const float4 xp = g_xyzp[blockIdx.x * BLOCK + tid];   // coalesced
    const float x = xp.x, y = xp.y, z = xp.z;
    const int p = __float_as_int(xp.w);
    sp[tid] = p;

    const unsigned P1 = 2654435761u;
    const unsigned P2 = 805459861u;

    float acc256 = b256s;

#pragma unroll
    for (int l = 0; l < L_LEVELS; l++) {
        const float resf = RESF[l];
        const float2* tl = tab + (size_t)l * T_SIZE;

        float px = x * resf, py = y * resf, pz = z * resf;
        float fx = floorf(px), fy = floorf(py), fz = floorf(pz);
        float tx = px - fx,   ty = py - fy,   tz = pz - fz;

        unsigned cx = (unsigned)fx, cy = (unsigned)fy, cz = (unsigned)fz;
        unsigned hx0 = cx,        hx1 = cx + 1u;
        unsigned hy0 = cy * P1,   hy1 = hy0 + P1;
        unsigned hz0 = cz * P2,   hz1 = hz0 + P2;

        float2 f[8];
        f[0] = __ldg(tl + ((hx0 ^ hy0 ^ hz0) & T_MASK));
        f[1] = __ldg(tl + ((hx0 ^ hy0 ^ hz1) & T_MASK));
        f[2] = __ldg(tl + ((hx0 ^ hy1 ^ hz0) & T_MASK));
        f[3] = __ldg(tl + ((hx0 ^ hy1 ^ hz1) & T_MASK));
        f[4] = __ldg(tl + ((hx1 ^ hy0 ^ hz0) & T_MASK));
        f[5] = __ldg(tl + ((hx1 ^ hy0 ^ hz1) & T_MASK));
        f[6] = __ldg(tl + ((hx1 ^ hy1 ^ hz0) & T_MASK));
        f[7] = __ldg(tl + ((hx1 ^ hy1 ^ hz1) & T_MASK));

        const float ux = 1.0f - tx, uy = 1.0f - ty, uz = 1.0f - tz;
        float wxy[4];
        wxy[0] = ux * uy;
        wxy[1] = ux * ty;
        wxy[2] = tx * uy;
        wxy[3] = tx * ty;

        float e0 = 0.0f, e1 = 0.0f;
#pragma unroll
        for (int i = 0; i < 8; i++) {
            float w = wxy[i >> 1] * ((i & 1) ? tz : uz);
            e0 = fmaf(w, f[i].x, e0);
            e1 = fmaf(w, f[i].y, e1);
        }

        *reinterpret_cast<float2*>(&semb[tid][2 * l]) = make_float2(e0, e1);
        acc256 = fmaf(e0, wc256[2 * l + 0], acc256);
        acc256 = fmaf(e1, wc256[2 * l + 1], acc256);
    }

    // odd 257th column
    __stcs(out + (size_t)p * D_OUT + 256, acc256);

    __syncthreads();

    // ------- Phase 2: GEMM head. Thread owns 4 strided columns. -------
    unsigned long long wreg[L_LEVELS][4];
#pragma unroll
    for (int kk = 0; kk < L_LEVELS; kk++) {
#pragma unroll
        for (int c = 0; c < 4; c++) {
            int col = tid + 64 * c;
            wreg[kk][c] = pack2(W[(2 * kk) * D_OUT + col], W[(2 * kk + 1) * D_OUT + col]);
        }
    }
    float breg[4];
#pragma unroll
    for (int c = 0; c < 4; c++) breg[c] = bias[tid + 64 * c];

#pragma unroll 2
    for (int r = 0; r < BLOCK; r++) {
        const float4* erow = reinterpret_cast<const float4*>(&semb[r][0]);
        unsigned long long a0 = 0, a1 = 0, a2 = 0, a3 = 0;
#pragma unroll
        for (int q = 0; q < 6; q++) {
            float4 e4 = erow[q];                 // broadcast LDS.128
            unsigned long long p0 = pack2(e4.x, e4.y);
            unsigned long long p1 = pack2(e4.z, e4.w);
            a0 = fma2(p0, wreg[2 * q][0], a0);  a0 = fma2(p1, wreg[2 * q + 1][0], a0);
            a1 = fma2(p0, wreg[2 * q][1], a1);  a1 = fma2(p1, wreg[2 * q + 1][1], a1);
            a2 = fma2(p0, wreg[2 * q][2], a2);  a2 = fma2(p1, wreg[2 * q + 1][2], a2);
            a3 = fma2(p0, wreg[2 * q][3], a3);  a3 = fma2(p1, wreg[2 * q + 1][3], a3);
        }
        float lo, hi;
        float* orow = out + (size_t)sp[r] * D_OUT;   // original row (128B-coalesced stores)
        unpack2(a0, lo, hi); __stcs(orow + tid,       lo + hi + breg[0]);
        unpack2(a1, lo, hi); __stcs(orow + tid +  64, lo + hi + breg[1]);
        unpack2(a2, lo, hi); __stcs(orow + tid + 128, lo + hi + breg[2]);
        unpack2(a3, lo, hi); __stcs(orow + tid + 192, lo + hi + breg[3]);
    }
}

extern "C" void kernel_launch(void* const* d_in, const int* in_sizes, int n_in,
                              void* d_out, int out_size) {
    const float*  xin  = (const float*) d_in[0];   // [N,3]
    const float2* tab  = (const float2*)d_in[1];   // [12,T,2] -> float2
    const float*  W    = (const float*) d_in[2];   // [24,257]
    const float*  bias = (const float*) d_in[3];   // [257]
    float* out = (float*)d_out;

    static void* hist_ptr = nullptr;
    if (!hist_ptr) cudaGetSymbolAddress(&hist_ptr, g_hist);

    cudaMemsetAsync(hist_ptr, 0, NBINS * sizeof(int));
    hist_kernel<<<N_POINTS / 256, 256>>>(xin);
    scan_kernel<<<1, 1024>>>();
    scatter_kernel<<<N_POINTS / 256, 256>>>(xin);
    hashgrid_fused_kernel<<<N_POINTS / BLOCK, BLOCK>>>(tab, W, bias, out);
}

// round 17
// speedup vs baseline: 1.1175x; 1.0647x over previous
#include <cuda_runtime.h>
#include <cstdint>

#define L_LEVELS 12
#define T_SIZE   (1u << 19)
#define T_MASK   (T_SIZE - 1u)
#define N_POINTS 524288
#define D_OUT    257
#define FEAT     24          // L * F
#define BLOCK    64          // threads per block = points per block (2 warps)
#define EMB_PAD  28          // padded row stride in floats

#define SORT_RES 32
#define NBINS    (SORT_RES * SORT_RES * SORT_RES)   // 32768
#define NCHUNK   32                                  // scan chunks (1024 bins each)

// ---------------- scratch (device globals: alloc-rule-safe) ----------------
__device__ int    g_hist[NBINS];
__device__ int    g_part[NCHUNK];
__device__ float4 g_xyzp[N_POINTS];   // sorted {x,y,z, bitcast(orig index)}

// ---------- packed f32x2 helpers (Blackwell FFMA2 path) ----------
__device__ __forceinline__ unsigned long long pack2(float lo, float hi) {
    unsigned long long r;
    asm("mov.b64 %0, {%1, %2};" : "=l"(r) : "f"(lo), "f"(hi));
    return r;
}
__device__ __forceinline__ void unpack2(unsigned long long v, float& lo, float& hi) {
    asm("mov.b64 {%0, %1}, %2;" : "=f"(lo), "=f"(hi) : "l"(v));
}
__device__ __forceinline__ unsigned long long fma2(unsigned long long a,
                                                   unsigned long long b,
                                                   unsigned long long c) {
    unsigned long long d;
    asm("fma.rn.f32x2 %0, %1, %2, %3;" : "=l"(d) : "l"(a), "l"(b), "l"(c));
    return d;
}

__device__ __constant__ float RESF[L_LEVELS] = {
    16.f, 24.f, 38.f, 60.f, 93.f, 145.f, 225.f, 350.f, 545.f, 847.f, 1317.f, 2048.f
};

__device__ __forceinline__ int cell_key(float x, float y, float z) {
    int cx = (int)(x * SORT_RES); cx = cx > SORT_RES - 1 ? SORT_RES - 1 : cx;
    int cy = (int)(y * SORT_RES); cy = cy > SORT_RES - 1 ? SORT_RES - 1 : cy;
    int cz = (int)(z * SORT_RES); cz = cz > SORT_RES - 1 ? SORT_RES - 1 : cz;
    return (cz * SORT_RES + cy) * SORT_RES + cx;
}

// -------- K1: histogram --------
__global__ void hist_kernel(const float* __restrict__ xin) {
    int p = blockIdx.x * blockDim.x + threadIdx.x;
    float x = xin[3 * p], y = xin[3 * p + 1], z = xin[3 * p + 2];
    atomicAdd(&g_hist[cell_key(x, y, z)], 1);
}

// -------- K2a: per-chunk totals (32 blocks x 1024) --------
__global__ void scan_reduce_kernel() {
    __shared__ int warp_sums[32];
    const int tid = threadIdx.x;
    const int lane = tid & 31, wid = tid >> 5;
    int v = g_hist[blockIdx.x * 1024 + tid];
    int s = v;
#pragma unroll
    for (int o = 16; o > 0; o >>= 1) s += __shfl_down_sync(0xffffffffu, s, o);
    if (lane == 0) warp_sums[wid] = s;
    __syncthreads();
    if (wid == 0) {
        int t = warp_sums[lane];
#pragma unroll
        for (int o = 16; o > 0; o >>= 1) t += __shfl_down_sync(0xffffffffu, t, o);
        if (lane == 0) g_part[blockIdx.x] = t;
    }
}

// -------- K2b: exclusive scan of the 32 chunk totals (1 warp) --------
__global__ void scan_part_kernel() {
    const int lane = threadIdx.x;
    int v = g_part[lane];
    int s = v;
#pragma unroll
    for (int o = 1; o < 32; o <<= 1) {
        int n = __shfl_up_sync(0xffffffffu, s, o);
        if (lane >= o) s += n;
    }
    g_part[lane] = s - v;   // exclusive
}

// -------- K2c: per-chunk exclusive scan + chunk base (32 blocks x 1024) ----
__global__ void scan_apply_kernel() {
    __shared__ int warp_sums[32];
    const int tid = threadIdx.x;
    const int lane = tid & 31, wid = tid >> 5;
    const int idx = blockIdx.x * 1024 + tid;
    int v = g_hist[idx];
    int s = v;
#pragma unroll
    for (int o = 1; o < 32; o <<= 1) {
        int n = __shfl_up_sync(0xffffffffu, s, o);
        if (lane >= o) s += n;
    }
    if (lane == 31) warp_sums[wid] = s;
    __syncthreads();
    if (wid == 0) {
        int ws = warp_sums[lane];
#pragma unroll
        for (int o = 1; o < 32; o <<= 1) {
            int n = __shfl_up_sync(0xffffffffu, ws, o);
            if (lane >= o) ws += n;
        }
        warp_sums[lane] = ws;
    }
    __syncthreads();
    int wbase = (wid > 0) ? warp_sums[wid - 1] : 0;
    g_hist[idx] = g_part[blockIdx.x] + wbase + s - v;   // global exclusive
}

// -------- K3: scatter into sorted order --------
__global__ void scatter_kernel(const float* __restrict__ xin) {
    int p = blockIdx.x * blockDim.x + threadIdx.x;
    float x = xin[3 * p], y = xin[3 * p + 1], z = xin[3 * p + 2];
    int pos = atomicAdd(&g_hist[cell_key(x, y, z)], 1);
    g_xyzp[pos] = make_float4(x, y, z, __int_as_float(p));
}

// -------- K4: main fused kernel (identical to R13/R14) --------
__global__ __launch_bounds__(BLOCK, 8)
void hashgrid_fused_kernel(const float2* __restrict__ tab,    // [12, T] of float2
                           const float*  __restrict__ W,      // [24, 257]
                           const float*  __restrict__ bias,   // [257]
                           float*        __restrict__ out)    // [N, 257]
{
    __shared__ float semb[BLOCK][EMB_PAD];
    __shared__ int   sp[BLOCK];            // original point index per row
    __shared__ float wc256[FEAT];
    __shared__ float b256s;

    const int tid = threadIdx.x;

    if (tid < FEAT) wc256[tid] = W[tid * D_OUT + 256];
    if (tid == FEAT) b256s = bias[256];
    __syncthreads();

    // ---------------- Phase 1: hash encode (thread = sorted point) -------------
    const float4 xp = g_xyzp[blockIdx.x * BLOCK + tid];   // coalesced
    const float x = xp.x, y = xp.y, z = xp.z;
    const int p = __float_as_int(xp.w);
    sp[tid] = p;

    const unsigned P1 = 2654435761u;
    const unsigned P2 = 805459861u;

    float acc256 = b256s;

#pragma unroll
    for (int l = 0; l < L_LEVELS; l++) {
        const float resf = RESF[l];
        const float2* tl = tab + (size_t)l * T_SIZE;

        float px = x * resf, py = y * resf, pz = z * resf;
        float fx = floorf(px), fy = floorf(py), fz = floorf(pz);
        float tx = px - fx,   ty = py - fy,   tz = pz - fz;

        unsigned cx = (unsigned)fx, cy = (unsigned)fy, cz = (unsigned)fz;
        unsigned hx0 = cx,        hx1 = cx + 1u;
        unsigned hy0 = cy * P1,   hy1 = hy0 + P1;
        unsigned hz0 = cz * P2,   hz1 = hz0 + P2;

        float2 f[8];
        f[0] = __ldg(tl + ((hx0 ^ hy0 ^ hz0) & T_MASK));
        f[1] = __ldg(tl + ((hx0 ^ hy0 ^ hz1) & T_MASK));
        f[2] = __ldg(tl + ((hx0 ^ hy1 ^ hz0) & T_MASK));
        f[3] = __ldg(tl + ((hx0 ^ hy1 ^ hz1) & T_MASK));
        f[4] = __ldg(tl + ((hx1 ^ hy0 ^ hz0) & T_MASK));
        f[5] = __ldg(tl + ((hx1 ^ hy0 ^ hz1) & T_MASK));
        f[6] = __ldg(tl + ((hx1 ^ hy1 ^ hz0) & T_MASK));
        f[7] = __ldg(tl + ((hx1 ^ hy1 ^ hz1) & T_MASK));

        const float ux = 1.0f - tx, uy = 1.0f - ty, uz = 1.0f - tz;
        float wxy[4];
        wxy[0] = ux * uy;
        wxy[1] = ux * ty;
        wxy[2] = tx * uy;
        wxy[3] = tx * ty;

        float e0 = 0.0f, e1 = 0.0f;
#pragma unroll
        for (int i = 0; i < 8; i++) {
            float w = wxy[i >> 1] * ((i & 1) ? tz : uz);
            e0 = fmaf(w, f[i].x, e0);
            e1 = fmaf(w, f[i].y, e1);
        }

        *reinterpret_cast<float2*>(&semb[tid][2 * l]) = make_float2(e0, e1);
        acc256 = fmaf(e0, wc256[2 * l + 0], acc256);
        acc256 = fmaf(e1, wc256[2 * l + 1], acc256);
    }

    // odd 257th column
    __stcs(out + (size_t)p * D_OUT + 256, acc256);

    __syncthreads();

    // ------- Phase 2: GEMM head. Thread owns 4 strided columns. -------
    unsigned long long wreg[L_LEVELS][4];
#pragma unroll
    for (int kk = 0; kk < L_LEVELS; kk++) {
#pragma unroll
        for (int c = 0; c < 4; c++) {
            int col = tid + 64 * c;
            wreg[kk][c] = pack2(W[(2 * kk) * D_OUT + col], W[(2 * kk + 1) * D_OUT + col]);
        }
    }
    float breg[4];
#pragma unroll
    for (int c = 0; c < 4; c++) breg[c] = bias[tid + 64 * c];

#pragma unroll 2
    for (int r = 0; r < BLOCK; r++) {
        const float4* erow = reinterpret_cast<const float4*>(&semb[r][0]);
        unsigned long long a0 = 0, a1 = 0, a2 = 0, a3 = 0;
#pragma unroll
        for (int q = 0; q < 6; q++) {
            float4 e4 = erow[q];                 // broadcast LDS.128
            unsigned long long p0 = pack2(e4.x, e4.y);
            unsigned long long p1 = pack2(e4.z, e4.w);
            a0 = fma2(p0, wreg[2 * q][0], a0);  a0 = fma2(p1, wreg[2 * q + 1][0], a0);
            a1 = fma2(p0, wreg[2 * q][1], a1);  a1 = fma2(p1, wreg[2 * q + 1][1], a1);
            a2 = fma2(p0, wreg[2 * q][2], a2);  a2 = fma2(p1, wreg[2 * q + 1][2], a2);
            a3 = fma2(p0, wreg[2 * q][3], a3);  a3 = fma2(p1, wreg[2 * q + 1][3], a3);
        }
        float lo, hi;
        float* orow = out + (size_t)sp[r] * D_OUT;   // original row (128B-coalesced stores)
        unpack2(a0, lo, hi); __stcs(orow + tid,       lo + hi + breg[0]);
        unpack2(a1, lo, hi); __stcs(orow + tid +  64, lo + hi + breg[1]);
        unpack2(a2, lo, hi); __stcs(orow + tid + 128, lo + hi + breg[2]);
        unpack2(a3, lo, hi); __stcs(orow + tid + 192, lo + hi + breg[3]);
    }
}

extern "C" void kernel_launch(void* const* d_in, const int* in_sizes, int n_in,
                              void* d_out, int out_size) {
    const float*  xin  = (const float*) d_in[0];   // [N,3]
    const float2* tab  = (const float2*)d_in[1];   // [12,T,2] -> float2
    const float*  W    = (const float*) d_in[2];   // [24,257]
    const float*  bias = (const float*) d_in[3];   // [257]
    float* out = (float*)d_out;

    static void* hist_ptr = nullptr;
    if (!hist_ptr) cudaGetSymbolAddress(&hist_ptr, g_hist);

    cudaMemsetAsync(hist_ptr, 0, NBINS * sizeof(int));
    hist_kernel<<<N_POINTS / 256, 256>>>(xin);
    scan_reduce_kernel<<<NCHUNK, 1024>>>();
    scan_part_kernel<<<1, 32>>>();
    scan_apply_kernel<<<NCHUNK, 1024>>>();
    scatter_kernel<<<N_POINTS / 256, 256>>>(xin);
    hashgrid_fused_kernel<<<N_POINTS / BLOCK, BLOCK>>>(tab, W, bias, out);
}